// round 10
// baseline (speedup 1.0000x reference)
#include <cuda_runtime.h>
#include <cstdint>

#define N_PTS 320
#define D_DIM 64
#define NPERM 1001
#define POCT 8
#define NOCT ((NPERM + POCT - 1) / POCT)    // 126
#define TOTROWS (NOCT * N_PTS)              // 40320
#define GRID_MAIN 296                       // 2 blocks/SM x 148 SMs, one wave
#define NWARP 10
#define NQ 5                                // qG,qS,qA,qB,qC per perm

__device__ float  dG[N_PTS * N_PTS];        // Gram (diag = nrm, kept)
__device__ float2 dSH[N_PTS * N_PTS];       // {S,H} = {(D0+D1)/2,(D0-D1)/2}, diag 0
__device__ float  dRowS[N_PTS];             // RowS_a = sum_{b!=a} S_ab
__device__ double dConsts[2];               // {C1 = sum_{a<b} S, Sn = sum nrm}
__device__ float  dL[NPERM];                // L_p = sum_a w_a RowS_a
__device__ float  dPart[GRID_MAIN][2][NWARP][POCT * NQ];

// ---------------------------------------------------------------------------
// K1: Gram matrix.
// ---------------------------------------------------------------------------
__global__ __launch_bounds__(N_PTS) void gram_kernel(const float* __restrict__ data) {
    __shared__ float4 xa[D_DIM / 4];
    int a = blockIdx.x, t = threadIdx.x;
    if (t < D_DIM / 4) xa[t] = reinterpret_cast<const float4*>(data)[a * (D_DIM / 4) + t];
    __syncthreads();
    const float4* xb = reinterpret_cast<const float4*>(data) + t * (D_DIM / 4);
    float acc = 0.f;
#pragma unroll
    for (int k = 0; k < D_DIM / 4; ++k) {
        float4 u = xa[k], v = __ldg(xb + k);
        acc = fmaf(u.x, v.x, acc); acc = fmaf(u.y, v.y, acc);
        acc = fmaf(u.z, v.z, acc); acc = fmaf(u.w, v.w, acc);
    }
    dG[a * N_PTS + t] = acc;
}

// ---------------------------------------------------------------------------
// K2: F-FREE tables. S=(D0+D1)/2, H=(D0-D1)/2 (diag zeroed), RowS.
// ---------------------------------------------------------------------------
__global__ __launch_bounds__(N_PTS) void tbuild_kernel() {
    __shared__ float sred[NWARP];
    int a = blockIdx.x, b = threadIdx.x;
    float G  = dG[a * N_PTS + b];
    float na = dG[a * (N_PTS + 1)], nb = dG[b * (N_PTS + 1)];
    float D0 = sqrtf(fmaxf(na + nb - 2.f * G, 0.f));
    float D1 = sqrtf(fmaxf(na + nb + 2.f * G, 0.f));
    float S  = (a == b) ? 0.f : (D0 + D1) * 0.5f;
    float H  = (a == b) ? 0.f : (D0 - D1) * 0.5f;
    dSH[a * N_PTS + b] = make_float2(S, H);

    float cc = S;
#pragma unroll
    for (int o = 16; o; o >>= 1) cc += __shfl_down_sync(0xffffffffu, cc, o);
    if ((b & 31) == 0) sred[b >> 5] = cc;
    __syncthreads();
    if (b == 0) {
        float s = 0.f;
#pragma unroll
        for (int w = 0; w < NWARP; ++w) s += sred[w];
        dRowS[a] = s;
    }
}

// ---------------------------------------------------------------------------
// K3: constants. C1 = 0.5*sum RowS, Sn = sum diag G (fp64).
// ---------------------------------------------------------------------------
__global__ __launch_bounds__(N_PTS) void consts_kernel() {
    __shared__ double sr[NWARP][2];
    int t = threadIdx.x;
    double c = (double)dRowS[t];
    double n = (double)dG[t * (N_PTS + 1)];
#pragma unroll
    for (int o = 16; o; o >>= 1) {
        c += __shfl_down_sync(0xffffffffu, c, o);
        n += __shfl_down_sync(0xffffffffu, n, o);
    }
    if ((t & 31) == 0) { sr[t >> 5][0] = c; sr[t >> 5][1] = n; }
    __syncthreads();
    if (t == 0) {
        double C = 0, S = 0;
#pragma unroll
        for (int w = 0; w < NWARP; ++w) { C += sr[w][0]; S += sr[w][1]; }
        dConsts[0] = 0.5 * C; dConsts[1] = S;
    }
}

// ---------------------------------------------------------------------------
// K4: per-perm linear term L_p = sum_i fs_i * RowS[sigma(i)].
// ---------------------------------------------------------------------------
__global__ __launch_bounds__(N_PTS) void lterm_kernel(
    const int* __restrict__ types, const float* __restrict__ faP,
    const float* __restrict__ bsP, const int* __restrict__ perms)
{
    __shared__ float sred[NWARP];
    int p = blockIdx.x, t = threadIdx.x;
    float fa = *faP, bs = *bsP;
    int pj = (p == 0) ? t : perms[(p - 1) * N_PTS + t];
    float w = (types[t] == 0) ? fa : bs;
    float cc = w * dRowS[pj];
#pragma unroll
    for (int o = 16; o; o >>= 1) cc += __shfl_down_sync(0xffffffffu, cc, o);
    if ((t & 31) == 0) sred[t >> 5] = cc;
    __syncthreads();
    if (t == 0) {
        float s = 0.f;
#pragma unroll
        for (int w2 = 0; w2 < NWARP; ++w2) s += sred[w2];
        dL[p] = s;
    }
}

// ---------------------------------------------------------------------------
// K5: main. Flat-span persistent over (oct,row); 8 perms per pass.
// Vectors: u_a = sInv (sign), w_a = fs of position sigma^{-1}(a), v = u*w.
// Accumulate cG=G*u, cS=S*w, cHu=H*u, cHv=H*v; dots at segment end.
// ---------------------------------------------------------------------------
__global__ __launch_bounds__(N_PTS, 2) void qmain_kernel(
    const float* __restrict__ faP, const float* __restrict__ bsP,
    const int* __restrict__ types, const int* __restrict__ perms)
{
    __shared__ float u8[N_PTS][POCT];
    __shared__ float w8[N_PTS][POCT];
    __shared__ float v8[N_PTS][POCT];

    const int blk = blockIdx.x;
    const int t = threadIdx.x;
    const int wid = t >> 5, lane = t & 31;
    const float fa = *faP, bs = *bsP;
    const int tt = types[t];
    const float fsv = (tt == 0) ? fa : bs;

    const int r0 = (int)(((long long)blk * TOTROWS) / GRID_MAIN);
    const int r1 = (int)(((long long)(blk + 1) * TOTROWS) / GRID_MAIN);

    int r = r0, seg = 0;
    while (r < r1) {
        const int oct = r / N_PTS;
        const int a0  = r - oct * N_PTS;
        const int aend = (a0 + (r1 - r) > N_PTS) ? N_PTS : a0 + (r1 - r);
        const int p0 = oct * POCT;

        // build u, w, v (scatter through sigma^{-1})
#pragma unroll
        for (int k = 0; k < POCT; ++k) {
            int p = p0 + k;
            int pj; float s, wv;
            if (p >= NPERM)      { pj = t; s = 0.f; wv = 0.f; }
            else if (p == 0)     { pj = t; s = 1.f; wv = fsv; }
            else {
                pj = perms[(p - 1) * N_PTS + t];
                int tp = types[pj];
                if (pj == t)                 s = 1.f;
                else if (tt == 0 && tp == 0) s = fa;
                else if (tt == 1 && tp == 1) s = bs;
                else                         s = 1.f;
                wv = fsv;
            }
            u8[pj][k] = s;
            w8[pj][k] = wv;
            v8[pj][k] = s * wv;
        }
        __syncthreads();

        float cG[POCT], cS[POCT], cHu[POCT], cHv[POCT];
#pragma unroll
        for (int k = 0; k < POCT; ++k) { cG[k] = cS[k] = cHu[k] = cHv[k] = 0.f; }

        const float*  gp  = dG  + a0 * N_PTS + t;
        const float2* shp = dSH + a0 * N_PTS + t;
#pragma unroll 4
        for (int a = a0; a < aend; ++a) {
            float4 ua = *reinterpret_cast<const float4*>(&u8[a][0]);
            float4 ub = *reinterpret_cast<const float4*>(&u8[a][4]);
            float4 wa = *reinterpret_cast<const float4*>(&w8[a][0]);
            float4 wb = *reinterpret_cast<const float4*>(&w8[a][4]);
            float4 va = *reinterpret_cast<const float4*>(&v8[a][0]);
            float4 vb = *reinterpret_cast<const float4*>(&v8[a][4]);
            float  gv = __ldg(gp);  gp  += N_PTS;
            float2 sh = __ldg(shp); shp += N_PTS;
            cG[0] = fmaf(ua.x, gv, cG[0]); cG[1] = fmaf(ua.y, gv, cG[1]);
            cG[2] = fmaf(ua.z, gv, cG[2]); cG[3] = fmaf(ua.w, gv, cG[3]);
            cG[4] = fmaf(ub.x, gv, cG[4]); cG[5] = fmaf(ub.y, gv, cG[5]);
            cG[6] = fmaf(ub.z, gv, cG[6]); cG[7] = fmaf(ub.w, gv, cG[7]);
            cS[0] = fmaf(wa.x, sh.x, cS[0]); cS[1] = fmaf(wa.y, sh.x, cS[1]);
            cS[2] = fmaf(wa.z, sh.x, cS[2]); cS[3] = fmaf(wa.w, sh.x, cS[3]);
            cS[4] = fmaf(wb.x, sh.x, cS[4]); cS[5] = fmaf(wb.y, sh.x, cS[5]);
            cS[6] = fmaf(wb.z, sh.x, cS[6]); cS[7] = fmaf(wb.w, sh.x, cS[7]);
            cHu[0] = fmaf(ua.x, sh.y, cHu[0]); cHu[1] = fmaf(ua.y, sh.y, cHu[1]);
            cHu[2] = fmaf(ua.z, sh.y, cHu[2]); cHu[3] = fmaf(ua.w, sh.y, cHu[3]);
            cHu[4] = fmaf(ub.x, sh.y, cHu[4]); cHu[5] = fmaf(ub.y, sh.y, cHu[5]);
            cHu[6] = fmaf(ub.z, sh.y, cHu[6]); cHu[7] = fmaf(ub.w, sh.y, cHu[7]);
            cHv[0] = fmaf(va.x, sh.y, cHv[0]); cHv[1] = fmaf(va.y, sh.y, cHv[1]);
            cHv[2] = fmaf(va.z, sh.y, cHv[2]); cHv[3] = fmaf(va.w, sh.y, cHv[3]);
            cHv[4] = fmaf(vb.x, sh.y, cHv[4]); cHv[5] = fmaf(vb.y, sh.y, cHv[5]);
            cHv[6] = fmaf(vb.z, sh.y, cHv[6]); cHv[7] = fmaf(vb.w, sh.y, cHv[7]);
        }

        // dots: qG=u.cG, qS=w.cS, qA=u.cHu, qB=v.cHu, qC=v.cHv
        float q[POCT * NQ];
#pragma unroll
        for (int k = 0; k < POCT; ++k) {
            float uo = u8[t][k], wo = w8[t][k], vo = v8[t][k];
            q[NQ * k + 0] = uo * cG[k];
            q[NQ * k + 1] = wo * cS[k];
            q[NQ * k + 2] = uo * cHu[k];
            q[NQ * k + 3] = vo * cHu[k];
            q[NQ * k + 4] = vo * cHv[k];
        }
#pragma unroll
        for (int k = 0; k < POCT * NQ; ++k) {
#pragma unroll
            for (int o = 16; o; o >>= 1)
                q[k] += __shfl_down_sync(0xffffffffu, q[k], o);
        }
        if (lane == 0) {
#pragma unroll
            for (int k = 0; k < POCT * NQ; ++k) dPart[blk][seg][wid][k] = q[k];
        }
        __syncthreads();
        r += aend - a0;
        ++seg;
    }
    for (; seg < 2; ++seg)
        if (lane == 0)
#pragma unroll
            for (int k = 0; k < POCT * NQ; ++k) dPart[blk][seg][wid][k] = 0.f;
}

// ---------------------------------------------------------------------------
// K6: finalize (fp64, fixed order).
//   Sd = N*Sn - qG
//   Sv = 0.5*C1 + 0.5*L - 0.25*qS + 0.25*qA + 0.5*qB - 0.25*qC
//   var = (Sd - Sv^2/M)/(M-1)
// ---------------------------------------------------------------------------
__global__ void finalize_kernel(float* __restrict__ out) {
    int p = blockIdx.x * blockDim.x + threadIdx.x;
    if (p >= NPERM) return;
    const int o = p >> 3, k = p & 7;
    const int rowLo = o * N_PTS, rowHi = rowLo + N_PTS;
    double qG = 0, qS = 0, qA = 0, qB = 0, qC = 0;
    for (int b = 0; b < GRID_MAIN; ++b) {
        int r0 = (int)(((long long)b * TOTROWS) / GRID_MAIN);
        int r1 = (int)(((long long)(b + 1) * TOTROWS) / GRID_MAIN);
        if (r1 <= rowLo || r0 >= rowHi) continue;
        int seg = (r0 >= rowLo) ? 0 : 1;
#pragma unroll
        for (int w = 0; w < NWARP; ++w) {
            const float* qq = &dPart[b][seg][w][NQ * k];
            qG += (double)qq[0]; qS += (double)qq[1];
            qA += (double)qq[2]; qB += (double)qq[3]; qC += (double)qq[4];
        }
    }
    const double M  = (double)(N_PTS * (N_PTS - 1) / 2);   // 51040
    const double C1 = dConsts[0], Sn = dConsts[1];
    double Sd = (double)N_PTS * Sn - qG;
    double Sv = 0.5 * C1 + 0.5 * (double)dL[p] - 0.25 * qS + 0.25 * qA + 0.5 * qB - 0.25 * qC;
    out[p] = (float)((Sd - Sv * Sv / M) / (M - 1.0));
}

// ---------------------------------------------------------------------------
extern "C" void kernel_launch(void* const* d_in, const int* in_sizes, int n_in,
                              void* d_out, int out_size) {
    const float* data  = (const float*)d_in[0];
    const float* fa    = (const float*)d_in[1];
    const float* bs    = (const float*)d_in[2];
    const int*   types = (const int*)d_in[3];
    const int*   perms = (const int*)d_in[4];
    float*       out   = (float*)d_out;

    gram_kernel<<<N_PTS, N_PTS>>>(data);
    tbuild_kernel<<<N_PTS, N_PTS>>>();
    consts_kernel<<<1, N_PTS>>>();
    lterm_kernel<<<NPERM, N_PTS>>>(types, fa, bs, perms);
    qmain_kernel<<<GRID_MAIN, N_PTS>>>(fa, bs, types, perms);
    finalize_kernel<<<(NPERM + 127) / 128, 128>>>(out);
}

// round 12
// speedup vs baseline: 1.5499x; 1.5499x over previous
#include <cuda_runtime.h>
#include <cstdint>

#define N_PTS 320
#define D_DIM 64
#define NPERM 1001                 // perm 0 = identity
#define NGRP  10                   // column groups of 32
#define BLK_T 160                  // 5 warps; warp w owns groups w and 9-w
#define NWARP_B (BLK_T / 32)       // 5

// Gram matrix of the ORIGINAL data: G[a][b] = <data[a], data[b]> (409.6 KB, L2-resident)
__device__ float dG[N_PTS * N_PTS];

// ---------------------------------------------------------------------------
// K1: Gram matrix. One block per row a; thread t computes G[a][t].
// ---------------------------------------------------------------------------
__global__ __launch_bounds__(N_PTS) void gram_kernel(const float* __restrict__ data) {
    __shared__ float4 xa[D_DIM / 4];
    int a = blockIdx.x, t = threadIdx.x;
    if (t < D_DIM / 4) xa[t] = reinterpret_cast<const float4*>(data)[a * (D_DIM / 4) + t];
    __syncthreads();
    const float4* xb = reinterpret_cast<const float4*>(data) + t * (D_DIM / 4);
    float acc = 0.f;
#pragma unroll
    for (int k = 0; k < D_DIM / 4; ++k) {
        float4 u = xa[k], v = __ldg(xb + k);
        acc = fmaf(u.x, v.x, acc); acc = fmaf(u.y, v.y, acc);
        acc = fmaf(u.z, v.z, acc); acc = fmaf(u.w, v.w, acc);
    }
    dG[a * N_PTS + t] = acc;
}

// ---------------------------------------------------------------------------
// K2: one block (160 threads, 5 warps) per permutation.
//
// Original-space pair formulation (sigma is a bijection):
//   sq(a,b) = nrm_a + nrm_b - 2 sInv[a] sInv[b] G[a,b]
//   F(a,b)  = max(fsInv[a], fsInv[b])      (exact for fa=-1, bs=+1)
//
// Warp w covers column-groups w and (9-w): trips = (32w+31)+(32(9-w)+31)=350
// for every warp -> exact intra-block balance with the cheap static loop body.
// Small blocks -> ~6.8 blocks/SM in ONE wave -> tiny tail (7 vs 6.76).
// ---------------------------------------------------------------------------
__device__ __forceinline__ void setup_meta(
    float4* meta, int p, int pos, float fa, float bs,
    const int* __restrict__ types, const int* __restrict__ perms)
{
    const int pj = (p == 0) ? pos : perms[(p - 1) * N_PTS + pos];
    const int tt = types[pos];
    const int tp = types[pj];
    float s;
    if (pj == pos)               s = 1.0f;
    else if (tt == 0 && tp == 0) s = fa;
    else if (tt == 1 && tp == 1) s = bs;
    else                         s = 1.0f;
    const float fsv = (tt == 0) ? fa : bs;
    meta[pj].x = s;                        // sInv
    meta[pj].y = fsv;                      // fsInv
    meta[pos].z = dG[pos * (N_PTS + 1)];   // nrm (natural index, sign-free)
}

__device__ __forceinline__ void triangle_col(
    const float4* __restrict__ meta, int col, float& accv, float& accd)
{
    const float4 mc = meta[col];
    const float m2  = -2.0f * mc.x;
    const float pn  = mc.z;
    const float fcl = mc.y;
    const float* gcol = dG + col;
#pragma unroll 4
    for (int a = 0; a < col; ++a) {
        float4 ma = meta[a];                  // broadcast LDS.128
        float gv  = __ldg(gcol + a * N_PTS);  // coalesced LDG (1 line / warp)
        float sg  = ma.x * gv;
        float ns  = pn + ma.z;
        float d2  = fmaf(m2, sg, ns);
        d2 = fmaxf(d2, 0.0f);
        float v;
        asm("sqrt.approx.f32 %0, %1;" : "=f"(v) : "f"(d2));
        float fm = fmaxf(fcl, ma.y);
        accv = fmaf(fm, v, accv);
        accd = fmaf(v, v, accd);
    }
}

__global__ __launch_bounds__(BLK_T) void qet_kernel(
    const float* __restrict__ faP, const float* __restrict__ bsP,
    const int* __restrict__ types, const int* __restrict__ perms,
    float* __restrict__ out)
{
    __shared__ float4 meta[N_PTS];
    __shared__ float2 sred[NWARP_B];

    const int p = blockIdx.x;
    const int t = threadIdx.x;

    const float fa = *faP;
    const float bs = *bsP;

    // each thread sets up two positions
    setup_meta(meta, p, t,         fa, bs, types, perms);
    setup_meta(meta, p, t + BLK_T, fa, bs, types, perms);
    __syncthreads();

    const int wid = t >> 5, lane = t & 31;

    float accv = 0.f;   // sum of F*val
    float accd = 0.f;   // sum of val^2 (F^2 == 1)

    // warp w: column-groups w and (NGRP-1 - w) -> 350 trips per warp
    triangle_col(meta, (wid << 5) + lane, accv, accd);
    triangle_col(meta, ((NGRP - 1 - wid) << 5) + lane, accv, accd);

    // block reduction (5 warps)
#pragma unroll
    for (int o = 16; o; o >>= 1) {
        accv += __shfl_down_sync(0xffffffffu, accv, o);
        accd += __shfl_down_sync(0xffffffffu, accd, o);
    }
    if (lane == 0) sred[wid] = make_float2(accv, accd);
    __syncthreads();
    if (t == 0) {
        double Sv = 0.0, Sd = 0.0;
#pragma unroll
        for (int w2 = 0; w2 < NWARP_B; ++w2) { Sv += sred[w2].x; Sd += sred[w2].y; }
        const double M = (double)(N_PTS * (N_PTS - 1) / 2);   // 51040
        out[p] = (float)((Sd - Sv * Sv / M) / (M - 1.0));
    }
}

// ---------------------------------------------------------------------------
// inputs: data[320*64] f32, fermion_antisymmetry f32[1], boson_symmetry f32[1],
// particle_types i32[320], perms i32[1000*320]; output: stats f32[1001]
// ---------------------------------------------------------------------------
extern "C" void kernel_launch(void* const* d_in, const int* in_sizes, int n_in,
                              void* d_out, int out_size) {
    const float* data  = (const float*)d_in[0];
    const float* fa    = (const float*)d_in[1];
    const float* bs    = (const float*)d_in[2];
    const int*   types = (const int*)d_in[3];
    const int*   perms = (const int*)d_in[4];
    float*       out   = (float*)d_out;

    gram_kernel<<<N_PTS, N_PTS>>>(data);
    qet_kernel<<<NPERM, BLK_T>>>(fa, bs, types, perms, out);
}

// round 14
// speedup vs baseline: 2.0810x; 1.3427x over previous
#include <cuda_runtime.h>
#include <cstdint>

#define N_PTS 320
#define D_DIM 64
#define NPERM 1001                 // perm 0 = identity
#define NPAIR ((NPERM + 1) / 2)    // 501 perm-pairs (last has a phantom)
#define NGRP  10
#define NWARP 10

// Gram matrix of the ORIGINAL data (409.6 KB, L2/L1-resident)
__device__ float dG[N_PTS * N_PTS];
// per (pair, parity): {accvA, accdA, accvB, accdB}
__device__ float4 dPart[NPAIR][2];

// ---------------------------------------------------------------------------
// K1: Gram matrix. One block per row a; thread t computes G[a][t].
// ---------------------------------------------------------------------------
__global__ __launch_bounds__(N_PTS) void gram_kernel(const float* __restrict__ data) {
    __shared__ float4 xa[D_DIM / 4];
    int a = blockIdx.x, t = threadIdx.x;
    if (t < D_DIM / 4) xa[t] = reinterpret_cast<const float4*>(data)[a * (D_DIM / 4) + t];
    __syncthreads();
    const float4* xb = reinterpret_cast<const float4*>(data) + t * (D_DIM / 4);
    float acc = 0.f;
#pragma unroll
    for (int k = 0; k < D_DIM / 4; ++k) {
        float4 u = xa[k], v = __ldg(xb + k);
        acc = fmaf(u.x, v.x, acc); acc = fmaf(u.y, v.y, acc);
        acc = fmaf(u.z, v.z, acc); acc = fmaf(u.w, v.w, acc);
    }
    dG[a * N_PTS + t] = acc;
}

// ---------------------------------------------------------------------------
// K2: block = (perm-pair q, row-parity par).  320 threads.
// Thread owns column c = 32*((wid+q)%10) + lane for BOTH perms of the pair,
// looping rows a = par, par+2, ... < c.  One G load serves both perms.
//   sq(a,c) = nrm_a + nrm_c - 2 s_a s_c G[a,c];  F = max(fs_a, fs_c)
// meta*[i] = { -2*s_i, fs_i, nrm_i, pad }   (scattered through sigma^{-1})
// ---------------------------------------------------------------------------
__global__ __launch_bounds__(N_PTS) void qet_kernel(
    const float* __restrict__ faP, const float* __restrict__ bsP,
    const int* __restrict__ types, const int* __restrict__ perms)
{
    __shared__ float4 mA[N_PTS];
    __shared__ float4 mB[N_PTS];
    __shared__ float4 sred[NWARP];

    const int q   = blockIdx.x >> 1;
    const int par = blockIdx.x & 1;
    const int t   = threadIdx.x;
    const int pA  = 2 * q;
    const int pB  = 2 * q + 1;

    const float fa = *faP;
    const float bs = *bsP;
    const int tt = types[t];
    const float fsv = (tt == 0) ? fa : bs;
    const float nrmT = dG[t * (N_PTS + 1)];

    // ---- meta A ----
    {
        int pj; float s;
        if (pA == 0) { pj = t; s = 1.f; }
        else {
            pj = perms[(pA - 1) * N_PTS + t];
            int tp = types[pj];
            if (pj == t)                 s = 1.f;
            else if (tt == 0 && tp == 0) s = fa;
            else if (tt == 1 && tp == 1) s = bs;
            else                         s = 1.f;
        }
        mA[pj].x = -2.f * s;
        mA[pj].y = fsv;
        mA[t].z  = nrmT;
    }
    // ---- meta B (phantom for pB >= NPERM: s = 0, keeps math finite) ----
    {
        int pj; float s;
        if (pB >= NPERM) { pj = t; s = 0.f; }
        else {
            pj = perms[(pB - 1) * N_PTS + t];
            int tp = types[pj];
            if (pj == t)                 s = 1.f;
            else if (tt == 0 && tp == 0) s = fa;
            else if (tt == 1 && tp == 1) s = bs;
            else                         s = 1.f;
        }
        mB[pj].x = -2.f * s;
        mB[pj].y = fsv;
        mB[t].z  = nrmT;
    }
    __syncthreads();

    const int wid = t >> 5, lane = t & 31;
    const int c = (((wid + q) % NGRP) << 5) + lane;   // R4 rotation

    const float4 mcA = mA[c];
    const float4 mcB = mB[c];
    const float sjA  = -0.5f * mcA.x;    // s_c^A
    const float sjB  = -0.5f * mcB.x;    // s_c^B
    const float fsjA = mcA.y;
    const float fsjB = mcB.y;
    const float pn   = mcA.z;            // nrm_c (perm-independent)

    float accvA = 0.f, accdA = 0.f, accvB = 0.f, accdB = 0.f;

    const float* gp = dG + c + par * N_PTS;
#pragma unroll 4
    for (int a = par; a < c; a += 2) {
        float4 maA = mA[a];                 // broadcast LDS.128
        float4 maB = mB[a];                 // broadcast LDS.128
        float  gv  = __ldg(gp);             // ONE coalesced LDG for both perms
        gp += 2 * N_PTS;
        float ns = pn + maA.z;              // shared

        float tA = sjA * gv;
        float dA = fmaf(maA.x, tA, ns);
        dA = fmaxf(dA, 0.f);
        float vA;
        asm("sqrt.approx.f32 %0, %1;" : "=f"(vA) : "f"(dA));
        float fmA = fmaxf(fsjA, maA.y);
        accvA = fmaf(fmA, vA, accvA);
        accdA = fmaf(vA, vA, accdA);

        float tB = sjB * gv;
        float dB = fmaf(maB.x, tB, ns);
        dB = fmaxf(dB, 0.f);
        float vB;
        asm("sqrt.approx.f32 %0, %1;" : "=f"(vB) : "f"(dB));
        float fmB = fmaxf(fsjB, maB.y);
        accvB = fmaf(fmB, vB, accvB);
        accdB = fmaf(vB, vB, accdB);
    }

    // block reduction (10 warps x 4 values)
#pragma unroll
    for (int o = 16; o; o >>= 1) {
        accvA += __shfl_down_sync(0xffffffffu, accvA, o);
        accdA += __shfl_down_sync(0xffffffffu, accdA, o);
        accvB += __shfl_down_sync(0xffffffffu, accvB, o);
        accdB += __shfl_down_sync(0xffffffffu, accdB, o);
    }
    if (lane == 0) sred[wid] = make_float4(accvA, accdA, accvB, accdB);
    __syncthreads();
    if (t == 0) {
        float4 s4 = make_float4(0.f, 0.f, 0.f, 0.f);
#pragma unroll
        for (int w = 0; w < NWARP; ++w) {
            s4.x += sred[w].x; s4.y += sred[w].y;
            s4.z += sred[w].z; s4.w += sred[w].w;
        }
        dPart[q][par] = s4;
    }
}

// ---------------------------------------------------------------------------
// K3: finalize. Combine the two parity blocks per perm (fp64, fixed order).
// ---------------------------------------------------------------------------
__global__ void finalize_kernel(float* __restrict__ out) {
    int p = blockIdx.x * blockDim.x + threadIdx.x;
    if (p >= NPERM) return;
    const int q = p >> 1, k = p & 1;
    float4 e = dPart[q][0];
    float4 o = dPart[q][1];
    double Sv, Sd;
    if (k == 0) { Sv = (double)e.x + (double)o.x; Sd = (double)e.y + (double)o.y; }
    else        { Sv = (double)e.z + (double)o.z; Sd = (double)e.w + (double)o.w; }
    const double M = (double)(N_PTS * (N_PTS - 1) / 2);   // 51040
    out[p] = (float)((Sd - Sv * Sv / M) / (M - 1.0));
}

// ---------------------------------------------------------------------------
// inputs: data[320*64] f32, fermion_antisymmetry f32[1], boson_symmetry f32[1],
// particle_types i32[320], perms i32[1000*320]; output: stats f32[1001]
// ---------------------------------------------------------------------------
extern "C" void kernel_launch(void* const* d_in, const int* in_sizes, int n_in,
                              void* d_out, int out_size) {
    const float* data  = (const float*)d_in[0];
    const float* fa    = (const float*)d_in[1];
    const float* bs    = (const float*)d_in[2];
    const int*   types = (const int*)d_in[3];
    const int*   perms = (const int*)d_in[4];
    float*       out   = (float*)d_out;

    gram_kernel<<<N_PTS, N_PTS>>>(data);
    qet_kernel<<<NPAIR * 2, N_PTS>>>(fa, bs, types, perms);
    finalize_kernel<<<(NPERM + 127) / 128, 128>>>(out);
}